// round 5
// baseline (speedup 1.0000x reference)
#include <cuda_runtime.h>
#include <cstdint>
#include <math.h>

#define NNI 32
#define CCI 256
#define HWI 1024
#define NPIX (NNI*HWI)
#define NBORD 124
#define NCHK 36

__device__ __align__(16) signed char g_Xs[2][(size_t)NPIX*256];   // NHWC int8 signs
__device__ __align__(16) signed char g_Ws[2][(size_t)9*256*256];  // W signs [tap][o][c]
__device__ uint32_t g_Xc2[2][NNI*32*256];                // bits [(n*32+h)*256+c], bit = w
__device__ unsigned long long g_Wp64[2][CCI*NCHK];
__device__ unsigned long long g_Vm[HWI*NCHK];
__device__ unsigned long long g_Xp[2][NNI*NBORD*NCHK];
__device__ short g_acc[2][(size_t)NNI*CCI*HWI];
__device__ long long g_S[2*CCI];
__device__ double g_Dd[2*CCI];
__device__ float g_coef[4*CCI];

__device__ __forceinline__ uint32_t s2u(const void* p){
    uint32_t a; asm("{ .reg .u64 t; cvta.to.shared.u64 t, %1; cvt.u32.u64 %0, t; }":"=r"(a):"l"(p)); return a;
}
__device__ __forceinline__ uint32_t lds(uint32_t a){
    uint32_t v; asm volatile("ld.shared.b32 %0,[%1];":"=r"(v):"r"(a)); return v;
}
__device__ __forceinline__ void imma(int* c, const uint32_t* a, const uint32_t* b){
    asm volatile("mma.sync.aligned.m16n8k32.row.col.s32.s8.s8.s32 "
        "{%0,%1,%2,%3},{%4,%5,%6,%7},{%8,%9},{%0,%1,%2,%3};"
        :"+r"(c[0]),"+r"(c[1]),"+r"(c[2]),"+r"(c[3])
        :"r"(a[0]),"r"(a[1]),"r"(a[2]),"r"(a[3]),"r"(b[0]),"r"(b[1]));
}
__device__ __forceinline__ void border_hw(int b,int&h,int&w){
    if(b<32){h=0;w=b;} else if(b<64){h=31;w=b-32;} else {int r=b-64;h=1+(r>>1);w=(r&1)?31:0;}
}
__device__ __forceinline__ long long wred_ll(long long v){for(int d=16;d;d>>=1)v+=__shfl_down_sync(0xffffffffu,v,d);return v;}
__device__ __forceinline__ double wred_d(double v){for(int d=16;d;d>>=1)v+=__shfl_down_sync(0xffffffffu,v,d);return v;}
__device__ __forceinline__ int wred_i(int v){for(int d=16;d;d>>=1)v+=__shfl_down_sync(0xffffffffu,v,d);return v;}

__global__ void k_zero(){ int t=threadIdx.x; if(t<2*CCI){g_S[t]=0;g_Dd[t]=0.0;} }

__global__ void k_pack_w(const float* __restrict__ w, int which){
    int o=blockIdx.x, j=threadIdx.x;
    if(j>=NCHK) return;
    unsigned long long bits=0ull;
    for(int b=0;b<64;b++){
        int f=64*j+b, c=f/9, k=f-9*c;
        bits |= (unsigned long long)(w[(size_t)(o*CCI+c)*9+k]>=0.f)<<b;
    }
    g_Wp64[which][o*NCHK+j]=bits;
}

__global__ void k_pack_ws(const float* __restrict__ w, int which){
    int o=blockIdx.x, c=threadIdx.x;
    const float* ws=w+((size_t)o*CCI+c)*9;
    #pragma unroll
    for(int tap=0;tap<9;tap++)
        g_Ws[which][(((size_t)tap*256+o)<<8)+c] = (ws[tap]>=0.f)?1:-1;
}

__global__ void k_vmask(){
    int hw=blockIdx.x, j=threadIdx.x;
    int h=hw>>5, w=hw&31;
    unsigned long long m=0ull;
    for(int b=0;b<64;b++){
        int f=64*j+b, k=f%9, kh=k/3, kw=k%3;
        int hh=h+kh-1, ww=w+kw-1;
        if((unsigned)hh<32u && (unsigned)ww<32u) m|=1ull<<b;
    }
    g_Vm[hw*NCHK+j]=m;
}

// transpose -> int8 NHWC signs + bit words. grid <<<1024,256>>>
__global__ void k_pack_xs(const float* __restrict__ x0, int which){
    __shared__ uint32_t tile[32][65];
    int blk=blockIdx.x; int n=blk>>5, h=blk&31;
    int t=threadIdx.x, p=t&31, cw=t>>5;
    for(int it=0;it<8;it++){
        int c0=it*32+cw*4;
        bool s[4];
        if(which==0){
            #pragma unroll
            for(int j=0;j<4;j++) s[j]= x0[(((size_t)n*256+c0+j)<<10)+(h<<5)+p]>=0.f;
        } else {
            #pragma unroll
            for(int j=0;j<4;j++){
                float v=(float)g_acc[0][(((size_t)n*256+c0+j)<<10)+(h<<5)+p];
                s[j]=(g_coef[c0+j]*v+g_coef[256+c0+j])>=0.f;
            }
        }
        uint32_t pk=0;
        #pragma unroll
        for(int j=0;j<4;j++) pk |= (uint32_t)(s[j]?0x01u:0xFFu)<<(8*j);
        tile[p][c0>>2]=pk;
        #pragma unroll
        for(int j=0;j<4;j++){
            uint32_t m=__ballot_sync(0xffffffffu,s[j]);
            if(p==0) g_Xc2[which][((size_t)blk<<8)+c0+j]=m;
        }
    }
    __syncthreads();
    int pp=t>>3, q=t&7;
    uint32_t* dst=(uint32_t*)&g_Xs[which][(((size_t)blk<<5)+pp)<<8];
    #pragma unroll
    for(int k=0;k<8;k++) dst[q*8+k]=tile[pp][q*8+k];
}

// ---- MAIN CONV: int8 mma.sync implicit GEMM. grid <<<256,256>>> ----
#define A_STR 272
#define B_STR 272
#define B_ROW (34*272)
#define SM_A_SZ (256*272)
#define SMEM_TOT (SM_A_SZ + 6*B_ROW)

__global__ void __launch_bounds__(256,1) k_conv_imma(int which){
    extern __shared__ char sm[];
    uint32_t smA=s2u(sm), smB=smA+SM_A_SZ;
    char* Ap=sm; char* Bp=sm+SM_A_SZ;
    int t=threadIdx.x, lane=t&31, warp=t>>5;
    int blk=blockIdx.x; int n=blk>>3, h0=(blk&7)<<2;
    int wm=warp>>1, wn=warp&1;

    // zero B halo, then copy valid rows (6 rows x 32px x 256B, cols shifted +1)
    for(int i=t;i<(6*B_ROW)/16;i+=256) ((uint4*)Bp)[i]=make_uint4(0,0,0,0);
    __syncthreads();
    for(int i=t;i<6*32*16;i+=256){
        int r=i>>9, rem=i&511, w=rem>>4, c4=rem&15;
        int hr=h0-1+r;
        if((unsigned)hr<32u){
            uint4 v=*(const uint4*)&g_Xs[which][((((size_t)n<<10)+(hr<<5)+w)<<8)+c4*16];
            *(uint4*)(Bp + r*B_ROW + (w+1)*B_STR + c4*16) = v;
        }
    }

    int acc[4][8][4];
    #pragma unroll
    for(int a=0;a<4;a++)
        #pragma unroll
        for(int b=0;b<8;b++)
            #pragma unroll
            for(int c=0;c<4;c++) acc[a][b][c]=0;

    uint32_t abase[4];
    #pragma unroll
    for(int mf=0;mf<4;mf++)
        abase[mf]=smA+(uint32_t)((wm*64+mf*16+(lane>>2))*A_STR+(lane&3)*4);

    for(int tap=0;tap<9;tap++){
        int dh=tap/3, dw=tap-3*dh;
        __syncthreads();
        for(int i=t;i<4096;i+=256){
            int o=i>>4, c4=i&15;
            uint4 v=*(const uint4*)&g_Ws[which][(((size_t)tap*256+o)<<8)+c4*16];
            *(uint4*)(Ap + o*A_STR + c4*16)=v;
        }
        __syncthreads();
        uint32_t bbase[8];
        #pragma unroll
        for(int nf=0;nf<8;nf++){
            int pix=wn*64+nf*8+(lane>>2);
            bbase[nf]=smB+(uint32_t)(((pix>>5)+dh)*B_ROW+((pix&31)+dw)*B_STR+(lane&3)*4);
        }
        #pragma unroll
        for(int ks=0;ks<8;ks++){
            int c=ks*32;
            uint32_t Af[4][4], Bf[8][2];
            #pragma unroll
            for(int mf=0;mf<4;mf++){
                uint32_t ab=abase[mf]+c;
                Af[mf][0]=lds(ab); Af[mf][1]=lds(ab+8*A_STR);
                Af[mf][2]=lds(ab+16); Af[mf][3]=lds(ab+8*A_STR+16);
            }
            #pragma unroll
            for(int nf=0;nf<8;nf++){
                uint32_t bb=bbase[nf]+c;
                Bf[nf][0]=lds(bb); Bf[nf][1]=lds(bb+16);
            }
            #pragma unroll
            for(int mf=0;mf<4;mf++)
                #pragma unroll
                for(int nf=0;nf<8;nf++) imma(acc[mf][nf],Af[mf],Bf[nf]);
        }
    }

    // epilogue: clip to +-254, store pairs of int16
    #pragma unroll
    for(int mf=0;mf<4;mf++)
        #pragma unroll
        for(int nf=0;nf<8;nf++){
            int row0=wm*64+mf*16+(lane>>2);
            int col=wn*64+nf*8+(lane&3)*2;
            int hr=h0+(col>>5), wc=col&31;
            #pragma unroll
            for(int hf=0;hf<2;hf++){
                int o=row0+hf*8;
                int v0=acc[mf][nf][hf*2], v1=acc[mf][nf][hf*2+1];
                v0=v0<-254?-254:(v0>254?254:v0);
                v1=v1<-254?-254:(v1>254?254:v1);
                uint32_t pk=(uint32_t)(unsigned short)(short)v0|((uint32_t)(unsigned short)(short)v1<<16);
                *(uint32_t*)&g_acc[which][(((size_t)n*256+o)<<10)+(hr<<5)+wc]=pk;
            }
        }
}

__global__ void k_border_pack(int which){
    int blk=blockIdx.x;
    int n=blk/NBORD, b=blk%NBORD;
    int h,w; border_hw(b,h,w);
    int j=threadIdx.x;
    if(j>=NCHK) return;
    unsigned long long bits=0ull;
    for(int bb=0;bb<64;bb++){
        int f=64*j+bb, c=f/9, k=f-9*c, kh=k/3, kw=k%3;
        int hh=h+kh-1, ww=w+kw-1;
        if((unsigned)hh<32u && (unsigned)ww<32u){
            uint32_t word=g_Xc2[which][(((size_t)(n*32+hh))<<8)+c];
            bits |= (unsigned long long)((word>>ww)&1u)<<bb;
        }
    }
    g_Xp[which][(size_t)(n*NBORD+b)*NCHK+j]=bits;
}

__global__ void k_conv_border(int which){
    __shared__ unsigned long long sxp[NCHK], svm[NCHK];
    __shared__ int svc[NCHK];
    int blk=blockIdx.x;
    int n=blk/NBORD, b=blk%NBORD;
    int h,w; border_hw(b,h,w);
    int t=threadIdx.x;
    if(t<NCHK){
        sxp[t]=g_Xp[which][(size_t)(n*NBORD+b)*NCHK+t];
        unsigned long long m=g_Vm[(h*32+w)*NCHK+t];
        svm[t]=m; svc[t]=__popcll(m);
    }
    __syncthreads();
    const unsigned long long* wp=&g_Wp64[which][t*NCHK];
    int acc=0;
    #pragma unroll
    for(int j=0;j<NCHK;j++){
        int mm=__popcll((sxp[j]^wp[j])&svm[j]);
        int ps=svc[j]-2*mm;
        acc += ps + ((ps&1)?((ps&2)-1):0);
    }
    acc = acc<-254?-254:(acc>254?254:acc);
    g_acc[which][(((size_t)n*CCI+t)<<10)+h*32+w]=(short)acc;
}

__global__ void k_bn1_stats(){
    int blk=blockIdx.x, c=blk&(CCI-1);
    const short* src=&g_acc[0][(size_t)blk*HWI];
    int t=threadIdx.x, s=0, q=0;
    for(int i=t;i<HWI;i+=256){ int v=src[i]; s+=v; q+=v*v; }
    __shared__ long long shs[8], shq[8];
    long long sl=wred_ll((long long)s), ql=wred_ll((long long)q);
    if((t&31)==0){ shs[t>>5]=sl; shq[t>>5]=ql; }
    __syncthreads();
    if(t==0){
        long long S=0,Q=0;
        for(int i=0;i<8;i++){S+=shs[i];Q+=shq[i];}
        atomicAdd((unsigned long long*)&g_S[2*c],(unsigned long long)S);
        atomicAdd((unsigned long long*)&g_S[2*c+1],(unsigned long long)Q);
    }
}

__global__ void k_coef1(const float* __restrict__ gamma, const float* __restrict__ beta){
    int c=threadIdx.x;
    double s=(double)g_S[2*c], q=(double)g_S[2*c+1];
    const double Nn=(double)(NNI*HWI);
    double m=s/Nn, var=q/Nn-m*m, rs=1.0/sqrt(var+1e-5), A=rs*(double)gamma[c];
    g_coef[c]=(float)A; g_coef[CCI+c]=(float)((double)beta[c]-m*A);
}

__global__ void k_bn2_stats(const float* __restrict__ x0){
    int blk=blockIdx.x, c=blk&(CCI-1);
    const short* a2=&g_acc[1][(size_t)blk*HWI];
    const float* xs=x0+(size_t)blk*HWI;
    int t=threadIdx.x;
    double s=0.0,q=0.0;
    for(int i=t;i<HWI;i+=256){ double y=(double)a2[i]+(double)xs[i]; s+=y; q+=y*y; }
    __shared__ double shs[8], shq[8];
    s=wred_d(s); q=wred_d(q);
    if((t&31)==0){ shs[t>>5]=s; shq[t>>5]=q; }
    __syncthreads();
    if(t==0){
        double S=0,Q=0;
        for(int i=0;i<8;i++){S+=shs[i];Q+=shq[i];}
        atomicAdd(&g_Dd[2*c],S); atomicAdd(&g_Dd[2*c+1],Q);
    }
}

__global__ void k_coef2(const float* __restrict__ gamma, const float* __restrict__ beta){
    int c=threadIdx.x;
    double s=g_Dd[2*c], q=g_Dd[2*c+1];
    const double Nn=(double)(NNI*HWI);
    double m=s/Nn, var=q/Nn-m*m, rs=1.0/sqrt(var+1e-5), A=rs*(double)gamma[c];
    g_coef[2*CCI+c]=(float)A; g_coef[3*CCI+c]=(float)((double)beta[c]-m*A);
}

__global__ void k_final(const float* __restrict__ x0, float* __restrict__ out){
    int blk=blockIdx.x, c=blk&(CCI-1);
    float A=g_coef[2*CCI+c], B=g_coef[3*CCI+c];
    const short* a2=&g_acc[1][(size_t)blk*HWI];
    const float* xs=x0+(size_t)blk*HWI;
    float* dst=out+(size_t)blk*HWI;
    for(int i=threadIdx.x;i<HWI;i+=256){
        float y=(float)a2[i]+xs[i];
        float z=A*y+B;
        dst[i]=fminf(1.f,fmaxf(-1.f,z));
    }
}

__global__ void k_reg(const float* __restrict__ reg0, float* __restrict__ out, int out_size){
    int t=threadIdx.x, cnt=0;
    for(int i=t;i<HWI*NCHK;i+=256) cnt+=(int)(__popcll(g_Vm[i])&1ull);
    __shared__ int sh[8];
    cnt=wred_i(cnt);
    if((t&31)==0) sh[t>>5]=cnt;
    __syncthreads();
    if(t==0){
        int T=0; for(int i=0;i<8;i++) T+=sh[i];
        out[out_size-1]=reg0[0]+3.0f*(float)T/1024.0f;
    }
}

extern "C" void kernel_launch(void* const* d_in, const int* in_sizes, int n_in,
                              void* d_out, int out_size){
    const float* x0=(const float*)d_in[0];
    const float* reg0=(const float*)d_in[1];
    const float* w1=(const float*)d_in[2];
    const float* gamma1=(const float*)d_in[3];
    const float* beta1=(const float*)d_in[4];
    const float* w2=(const float*)d_in[5];
    const float* gamma2=(const float*)d_in[6];
    const float* beta2=(const float*)d_in[7];
    float* out=(float*)d_out;

    cudaFuncSetAttribute(k_conv_imma, cudaFuncAttributeMaxDynamicSharedMemorySize, SMEM_TOT);

    k_zero<<<1,512>>>();
    k_pack_w<<<256,64>>>(w1,0);
    k_pack_w<<<256,64>>>(w2,1);
    k_pack_ws<<<256,256>>>(w1,0);
    k_pack_ws<<<256,256>>>(w2,1);
    k_vmask<<<HWI,NCHK>>>();
    k_pack_xs<<<1024,256>>>(x0,0);

    k_conv_imma<<<256,256,SMEM_TOT>>>(0);
    k_border_pack<<<NNI*NBORD,64>>>(0);
    k_conv_border<<<NNI*NBORD,256>>>(0);

    k_bn1_stats<<<NNI*CCI,256>>>();
    k_coef1<<<1,256>>>(gamma1,beta1);
    k_pack_xs<<<1024,256>>>(x0,1);

    k_conv_imma<<<256,256,SMEM_TOT>>>(1);
    k_border_pack<<<NNI*NBORD,64>>>(1);
    k_conv_border<<<NNI*NBORD,256>>>(1);

    k_bn2_stats<<<NNI*CCI,256>>>(x0);
    k_coef2<<<1,256>>>(gamma2,beta2);
    k_final<<<NNI*CCI,256>>>(x0,out);

    k_reg<<<1,256>>>(reg0,out,out_size);
}

// round 6
// speedup vs baseline: 1.7525x; 1.7525x over previous
#include <cuda_runtime.h>
#include <cstdint>
#include <math.h>

#define NNI   32
#define CCI   256
#define HWI   1024
#define NPIX  (NNI*HWI)
#define NBORD 124
#define NCHK  36

// ---------------- static device scratch ----------------
__device__ uint32_t           g_X32[2][NPIX*8];     // sign bits, channel-packed per pixel
__device__ uint32_t           g_Wc32[2][CCI*72];    // weights channel-packed [o][k*8+q]
__device__ unsigned long long g_Wp64[2][CCI*NCHK];  // weights patch-flat [o][chunk]
__device__ unsigned long long g_Vm[HWI*NCHK];       // validity mask per (h,w) per chunk
__device__ short              g_acc[2][NNI*CCI*HWI];
__device__ float              g_coef[4*CCI];        // A1,B1,A2,B2

// ---------------- helpers ----------------
__device__ __forceinline__ void border_hw(int b, int& h, int& w){
    if (b < 32)       { h = 0;  w = b; }
    else if (b < 64)  { h = 31; w = b - 32; }
    else              { int r = b - 64; h = 1 + (r >> 1); w = (r & 1) ? 31 : 0; }
}
__device__ __forceinline__ long long wred_ll(long long v){
    for (int d = 16; d; d >>= 1) v += __shfl_down_sync(0xffffffffu, v, d);
    return v;
}
__device__ __forceinline__ double wred_d(double v){
    for (int d = 16; d; d >>= 1) v += __shfl_down_sync(0xffffffffu, v, d);
    return v;
}
__device__ __forceinline__ int wred_i(int v){
    for (int d = 16; d; d >>= 1) v += __shfl_down_sync(0xffffffffu, v, d);
    return v;
}

// validity of the 9 taps for pixel (h,w) folded into the 64-bit chunk mask
__device__ __forceinline__ unsigned long long vmask_of(int h, int w, int j){
    const unsigned long long BASE = 0x8040201008040201ull; // bits == 0 mod 9
    int o9 = (64*j) % 9;
    unsigned long long m = 0ull;
    #pragma unroll
    for (int k = 0; k < 9; k++){
        int kh = k/3, kw = k - 3*kh;
        int hh = h + kh - 1, ww = w + kw - 1;
        if ((unsigned)hh < 32u && (unsigned)ww < 32u){
            int r = k - o9; if (r < 0) r += 9;
            m |= BASE << r;
        }
    }
    return m;
}

// ---------------- pack both weight tensors (both layouts). grid <<<512,128>>> ----------------
__global__ void k_pack_w(const float* __restrict__ w1, const float* __restrict__ w2){
    int blk = blockIdx.x;
    int which = blk >> 8, o = blk & 255, t = threadIdx.x;
    const float* w = which ? w2 : w1;
    if (t < 72){
        int k = t >> 3, q2 = t & 7;
        uint32_t bits = 0;
        for (int b = 0; b < 32; b++){
            int c = q2*32 + b;
            bits |= (uint32_t)(w[(size_t)(o*CCI + c)*9 + k] >= 0.f) << b;
        }
        g_Wc32[which][o*72 + t] = bits;
    } else if (t < 72 + NCHK){
        int j = t - 72;
        unsigned long long bits = 0ull;
        for (int b = 0; b < 64; b++){
            int f = 64*j + b;
            int c = f / 9, k = f - 9*c;
            bits |= (unsigned long long)(w[(size_t)(o*CCI + c)*9 + k] >= 0.f) << b;
        }
        g_Wp64[which][o*NCHK + j] = bits;
    }
}

// ---------------- validity masks (closed form). grid <<<1024,36>>> ----------------
__global__ void k_vmask(){
    int hw = blockIdx.x, j = threadIdx.x;
    g_Vm[hw*NCHK + j] = vmask_of(hw >> 5, hw & 31, j);
}

// ---------------- pack x0 sign bits. grid <<<128,256>>> ----------------
__global__ void k_pack_x1(const float* __restrict__ x){
    int p = blockIdx.x*blockDim.x + threadIdx.x;
    if (p >= NPIX) return;
    int n = p >> 10, hw = p & 1023;
    const float* src = x + (size_t)n*CCI*HWI + hw;
    uint32_t wd[8] = {0,0,0,0,0,0,0,0};
    for (int c = 0; c < CCI; c++){
        uint32_t bit = (src[(size_t)c*HWI] >= 0.f);
        wd[c >> 5] |= bit << (c & 31);
    }
    #pragma unroll
    for (int q = 0; q < 8; q++) g_X32[0][p*8 + q] = wd[q];
}

// ---------------- pack sign(bn1(acc1)) bits. grid <<<128,256>>> ----------------
__global__ void k_pack_x2(){
    int p = blockIdx.x*blockDim.x + threadIdx.x;
    if (p >= NPIX) return;
    int n = p >> 10, hw = p & 1023;
    uint32_t wd[8] = {0,0,0,0,0,0,0,0};
    for (int c = 0; c < CCI; c++){
        float v = (float)g_acc[0][(size_t)(n*CCI + c)*HWI + hw];
        float z = g_coef[c]*v + g_coef[CCI + c];
        uint32_t bit = (z >= 0.f);
        wd[c >> 5] |= bit << (c & 31);
    }
    #pragma unroll
    for (int q = 0; q < 8; q++) g_X32[1][p*8 + q] = wd[q];
}

// ---------------- interior conv: XNOR-popcount. grid <<<1920,256>>> ----------------
__global__ void __launch_bounds__(256) k_conv_int(int which){
    __shared__ uint32_t sw[128*72];
    __shared__ uint32_t sx[3*256];
    int blk   = blockIdx.x;
    int ohalf = blk & 1;
    int nh    = blk >> 1;
    int n = nh / 30, h = 1 + nh % 30;
    int t = threadIdx.x;

    for (int i = t; i < 128*72; i += 256) sw[i] = g_Wc32[which][ohalf*128*72 + i];
    {
        const uint32_t* base = &g_X32[which][((size_t)(n*32 + (h-1))*32) * 8];
        for (int i = t; i < 3*256; i += 256) sx[i] = base[i];
    }
    __syncthreads();

    int wq = t & 31;
    int og = t >> 5;
    if (wq < 1 || wq > 30) return;

    uint32_t xr[72];
    #pragma unroll
    for (int kh = 0; kh < 3; kh++)
        #pragma unroll
        for (int kw = 0; kw < 3; kw++)
            #pragma unroll
            for (int q = 0; q < 8; q++)
                xr[(kh*3 + kw)*8 + q] = sx[kh*256 + (wq + kw - 1)*8 + q];

    short* dst = &g_acc[which][(size_t)n*CCI*HWI + h*32 + wq];
    for (int i = 0; i < 16; i++){
        int o_local = og*16 + i;
        const uint32_t* wr = &sw[o_local*72];
        int mm = 0;
        #pragma unroll
        for (int u = 0; u < 72; u++) mm += __popc(xr[u] ^ wr[u]);
        int D = 2304 - 2*mm;
        D = D < -254 ? -254 : (D > 254 ? 254 : D);
        int o = ohalf*128 + o_local;
        dst[(size_t)o*HWI] = (short)D;
    }
}

// ---------------- border: fused patch-gather + quantized conv. grid <<<3968,256>>> ----------------
__global__ void k_border(int which){
    __shared__ unsigned long long sxp[NCHK], svm[NCHK];
    __shared__ int svc[NCHK];
    int blk = blockIdx.x;
    int n = blk / NBORD, b = blk % NBORD;
    int h, w; border_hw(b, h, w);
    int t = threadIdx.x;

    if (t < NCHK) sxp[t] = 0ull;
    __syncthreads();

    if (t < 144){                      // 4 threads per chunk, 16 bits each
        int j = t >> 2, q = t & 3;
        unsigned long long bits = 0ull;
        for (int bb = q*16; bb < q*16 + 16; bb++){
            int f = 64*j + bb;
            int c = f / 9, k = f - 9*c;
            int kh = k / 3, kw = k % 3;
            int hh = h + kh - 1, ww = w + kw - 1;
            if ((unsigned)hh < 32u && (unsigned)ww < 32u){
                uint32_t word = g_X32[which][(((n*32 + hh)*32 + ww) << 3) + (c >> 5)];
                bits |= (unsigned long long)((word >> (c & 31)) & 1u) << bb;
            }
        }
        atomicOr(&sxp[j], bits);
    } else if (t < 144 + NCHK){
        int j = t - 144;
        unsigned long long m = vmask_of(h, w, j);
        svm[j] = m;
        svc[j] = __popcll(m);
    }
    __syncthreads();

    int o = t;
    const unsigned long long* wp = &g_Wp64[which][o*NCHK];
    int acc = 0;
    #pragma unroll
    for (int j = 0; j < NCHK; j++){
        int mm = __popcll((sxp[j] ^ wp[j]) & svm[j]);
        int ps = svc[j] - 2*mm;
        acc += ps + ((ps & 1) ? ((ps & 2) - 1) : 0);
    }
    acc = acc < -254 ? -254 : (acc > 254 ? 254 : acc);
    g_acc[which][(size_t)(n*CCI + o)*HWI + h*32 + w] = (short)acc;
}

// ---------------- bn1: stats + coef fused. grid <<<256,512>>> ----------------
__global__ void k_bn1(const float* __restrict__ gamma, const float* __restrict__ beta){
    int c = blockIdx.x, t = threadIdx.x;
    int s = 0, q = 0;
    for (int n = 0; n < NNI; n++){
        uint32_t pk = *(const uint32_t*)&g_acc[0][(((size_t)n*CCI + c) << 10) + 2*t];
        int v0 = (short)(pk & 0xFFFF), v1 = (short)(pk >> 16);
        s += v0 + v1; q += v0*v0 + v1*v1;
    }
    __shared__ long long shs[16], shq[16];
    long long sl = wred_ll((long long)s), ql = wred_ll((long long)q);
    if ((t & 31) == 0){ shs[t >> 5] = sl; shq[t >> 5] = ql; }
    __syncthreads();
    if (t == 0){
        long long S = 0, Q = 0;
        for (int i = 0; i < 16; i++){ S += shs[i]; Q += shq[i]; }
        const double Nn = (double)(NNI*HWI);
        double m   = (double)S / Nn;
        double var = (double)Q / Nn - m*m;
        double A   = (1.0 / sqrt(var + 1e-5)) * (double)gamma[c];
        g_coef[c]       = (float)A;
        g_coef[CCI + c] = (float)((double)beta[c] - m*A);
    }
}

// ---------------- bn2: stats + coef fused (over clip(acc2)+x0). grid <<<256,512>>> ----------------
__global__ void k_bn2(const float* __restrict__ x0,
                      const float* __restrict__ gamma, const float* __restrict__ beta){
    int c = blockIdx.x, t = threadIdx.x;
    double s = 0.0, q = 0.0;
    for (int n = 0; n < NNI; n++){
        size_t base = (((size_t)n*CCI + c) << 10) + 2*t;
        uint32_t pk = *(const uint32_t*)&g_acc[1][base];
        float2 xv = *(const float2*)&x0[base];
        double y0 = (double)(short)(pk & 0xFFFF) + (double)xv.x;
        double y1 = (double)(short)(pk >> 16)    + (double)xv.y;
        s += y0 + y1; q += y0*y0 + y1*y1;
    }
    __shared__ double shs[16], shq[16];
    s = wred_d(s); q = wred_d(q);
    if ((t & 31) == 0){ shs[t >> 5] = s; shq[t >> 5] = q; }
    __syncthreads();
    if (t == 0){
        double S = 0, Q = 0;
        for (int i = 0; i < 16; i++){ S += shs[i]; Q += shq[i]; }
        const double Nn = (double)(NNI*HWI);
        double m   = S / Nn;
        double var = Q / Nn - m*m;
        double A   = (1.0 / sqrt(var + 1e-5)) * (double)gamma[c];
        g_coef[2*CCI + c] = (float)A;
        g_coef[3*CCI + c] = (float)((double)beta[c] - m*A);
    }
}

// ---------------- final: bn2 + hardtanh. grid <<<8192,256>>> ----------------
__global__ void k_final(const float* __restrict__ x0, float* __restrict__ out){
    int blk = blockIdx.x;
    int c = blk & (CCI - 1);
    float A = g_coef[2*CCI + c], B = g_coef[3*CCI + c];
    const short* a2 = &g_acc[1][(size_t)blk*HWI];
    const float* xs = x0 + (size_t)blk*HWI;
    float* dst = out + (size_t)blk*HWI;
    for (int i = threadIdx.x; i < HWI; i += 256){
        float y = (float)a2[i] + xs[i];
        float z = A*y + B;
        dst[i] = fminf(1.f, fmaxf(-1.f, z));
    }
}

// ---------------- regularizer. <<<1,256>>> ----------------
__global__ void k_reg(const float* __restrict__ reg0, float* __restrict__ out, int out_size){
    int t = threadIdx.x, cnt = 0;
    for (int i = t; i < HWI*NCHK; i += 256) cnt += (int)(__popcll(g_Vm[i]) & 1ull);
    __shared__ int sh[8];
    cnt = wred_i(cnt);
    if ((t & 31) == 0) sh[t >> 5] = cnt;
    __syncthreads();
    if (t == 0){
        int T = 0;
        for (int i = 0; i < 8; i++) T += sh[i];
        out[out_size - 1] = reg0[0] + 3.0f * (float)T / 1024.0f;
    }
}

// ---------------- launch ----------------
extern "C" void kernel_launch(void* const* d_in, const int* in_sizes, int n_in,
                              void* d_out, int out_size){
    const float* x0     = (const float*)d_in[0];
    const float* reg0   = (const float*)d_in[1];
    const float* w1     = (const float*)d_in[2];
    const float* gamma1 = (const float*)d_in[3];
    const float* beta1  = (const float*)d_in[4];
    const float* w2     = (const float*)d_in[5];
    const float* gamma2 = (const float*)d_in[6];
    const float* beta2  = (const float*)d_in[7];
    float* out = (float*)d_out;

    k_pack_w<<<512, 128>>>(w1, w2);          // 0
    k_vmask<<<HWI, NCHK>>>();                // 1
    k_pack_x1<<<128, 256>>>(x0);             // 2
    k_conv_int<<<NNI*30*2, 256>>>(0);        // 3  <-- profiled slot
    k_border<<<NNI*NBORD, 256>>>(0);         // 4
    k_bn1<<<256, 512>>>(gamma1, beta1);      // 5
    k_pack_x2<<<128, 256>>>();               // 6
    k_conv_int<<<NNI*30*2, 256>>>(1);        // 7
    k_border<<<NNI*NBORD, 256>>>(1);         // 8
    k_bn2<<<256, 512>>>(x0, gamma2, beta2);  // 9
    k_final<<<NNI*CCI, 256>>>(x0, out);      // 10
    k_reg<<<1, 256>>>(reg0, out, out_size);  // 11
}

// round 7
// speedup vs baseline: 1.9225x; 1.0970x over previous
#include <cuda_runtime.h>
#include <cstdint>
#include <math.h>

#define NNI   32
#define CCI   256
#define HWI   1024
#define NPIX  (NNI*HWI)
#define NBORD 124
#define NCHK  36

// ---------------- static device scratch ----------------
__device__ uint32_t           g_X32[2][NPIX*8];     // sign bits, channel-packed per pixel
__device__ uint32_t           g_Wc32[2][CCI*72];    // weights channel-packed [o][k*8+q]
__device__ unsigned long long g_Wp64[2][CCI*NCHK];  // weights patch-flat [o][chunk]
__device__ unsigned long long g_Vm[HWI*NCHK];       // validity mask per (h,w) per chunk
__device__ short              g_acc[2][NNI*CCI*HWI];
__device__ float              g_coef[4*CCI];        // A1,B1,A2,B2

// ---------------- helpers ----------------
__device__ __forceinline__ void border_hw(int b, int& h, int& w){
    if (b < 32)       { h = 0;  w = b; }
    else if (b < 64)  { h = 31; w = b - 32; }
    else              { int r = b - 64; h = 1 + (r >> 1); w = (r & 1) ? 31 : 0; }
}
__device__ __forceinline__ long long wred_ll(long long v){
    for (int d = 16; d; d >>= 1) v += __shfl_down_sync(0xffffffffu, v, d);
    return v;
}
__device__ __forceinline__ double wred_d(double v){
    for (int d = 16; d; d >>= 1) v += __shfl_down_sync(0xffffffffu, v, d);
    return v;
}
__device__ __forceinline__ int wred_i(int v){
    for (int d = 16; d; d >>= 1) v += __shfl_down_sync(0xffffffffu, v, d);
    return v;
}

// validity of the 9 taps folded into the 64-bit chunk mask (closed form)
__device__ __forceinline__ unsigned long long vmask_of(int h, int w, int j){
    const unsigned long long BASE = 0x8040201008040201ull; // bits == 0 mod 9
    int o9 = (64*j) % 9;
    unsigned long long m = 0ull;
    #pragma unroll
    for (int k = 0; k < 9; k++){
        int kh = k/3, kw = k - 3*kh;
        int hh = h + kh - 1, ww = w + kw - 1;
        if ((unsigned)hh < 32u && (unsigned)ww < 32u){
            int r = k - o9; if (r < 0) r += 9;
            m |= BASE << r;
        }
    }
    return m;
}

// ---------------- pack both weight tensors (both layouts). grid <<<512,128>>> ----------------
__global__ void k_pack_w(const float* __restrict__ w1, const float* __restrict__ w2){
    int blk = blockIdx.x;
    int which = blk >> 8, o = blk & 255, t = threadIdx.x;
    const float* w = which ? w2 : w1;
    if (t < 72){
        int k = t >> 3, q2 = t & 7;
        uint32_t bits = 0;
        for (int b = 0; b < 32; b++){
            int c = q2*32 + b;
            bits |= (uint32_t)(w[(size_t)(o*CCI + c)*9 + k] >= 0.f) << b;
        }
        g_Wc32[which][o*72 + t] = bits;
    } else if (t < 72 + NCHK){
        int j = t - 72;
        unsigned long long bits = 0ull;
        for (int b = 0; b < 64; b++){
            int f = 64*j + b;
            int c = f / 9, k = f - 9*c;
            bits |= (unsigned long long)(w[(size_t)(o*CCI + c)*9 + k] >= 0.f) << b;
        }
        g_Wp64[which][o*NCHK + j] = bits;
    }
}

// ---------------- validity masks. grid <<<1024,36>>> ----------------
__global__ void k_vmask(){
    int hw = blockIdx.x, j = threadIdx.x;
    g_Vm[hw*NCHK + j] = vmask_of(hw >> 5, hw & 31, j);
}

// ---------------- pack x0: coalesced + ballot + bit transpose. grid <<<1024,256>>> ----------------
__global__ void k_pack_x1(const float* __restrict__ x){
    __shared__ uint32_t sB[256];      // [c]: bit w = sign(x[n,c,h,w])
    int blk = blockIdx.x;             // n*32 + h
    int n = blk >> 5, h = blk & 31;
    int t = threadIdx.x, warp = t >> 5, lane = t & 31;
    for (int it = 0; it < 32; it++){
        int c = warp*32 + it;
        float v = x[(((size_t)n*CCI + c) << 10) + (h << 5) + lane];
        uint32_t m = __ballot_sync(0xffffffffu, v >= 0.f);
        if (lane == 0) sB[c] = m;
    }
    __syncthreads();
    int p = t & 31, q = t >> 5;
    uint32_t wd = 0;
    #pragma unroll
    for (int b = 0; b < 32; b++) wd |= ((sB[q*32 + b] >> p) & 1u) << b;
    g_X32[0][((size_t)(blk*32 + p))*8 + q] = wd;
}

// ---------------- pack sign(bn1(acc1)): coalesced + ballot + transpose. grid <<<1024,256>>> ----------------
__global__ void k_pack_x2(){
    __shared__ uint32_t sB[256];
    int blk = blockIdx.x;
    int n = blk >> 5, h = blk & 31;
    int t = threadIdx.x, warp = t >> 5, lane = t & 31;
    for (int it = 0; it < 32; it++){
        int c = warp*32 + it;
        float A = g_coef[c], B = g_coef[CCI + c];
        float v = (float)g_acc[0][(((size_t)n*CCI + c) << 10) + (h << 5) + lane];
        uint32_t m = __ballot_sync(0xffffffffu, (A*v + B) >= 0.f);
        if (lane == 0) sB[c] = m;
    }
    __syncthreads();
    int p = t & 31, q = t >> 5;
    uint32_t wd = 0;
    #pragma unroll
    for (int b = 0; b < 32; b++) wd |= ((sB[q*32 + b] >> p) & 1u) << b;
    g_X32[1][((size_t)(blk*32 + p))*8 + q] = wd;
}

// ---------------- interior conv: XNOR-popcount, conflict-free smem. grid <<<1920,256>>> ----------------
__global__ void __launch_bounds__(256) k_conv_int(int which){
    __shared__ uint32_t sw[128*72];        // [o_local][k*8+q], rows 288B (16B aligned)
    __shared__ uint32_t sx[8*102];         // [q][kh*34 + col]: lanes read consecutive cols
    int blk   = blockIdx.x;
    int ohalf = blk & 1;
    int nh    = blk >> 1;
    int n = nh / 30, h = 1 + nh % 30;
    int t = threadIdx.x;

    for (int i = t; i < 128*72; i += 256) sw[i] = g_Wc32[which][ohalf*128*72 + i];
    {
        const uint32_t* base = &g_X32[which][((size_t)(n*32 + (h-1))*32) * 8];
        for (int i = t; i < 768; i += 256){
            int kh = i >> 8, rem = i & 255, col = rem >> 3, q = rem & 7;
            sx[q*102 + kh*34 + col] = base[i];   // base[kh*256 + col*8 + q] == base[i]
        }
    }
    __syncthreads();

    int wq = t & 31;          // output column
    int og = t >> 5;          // warp id: o-group (8 x 16)
    if (wq < 1 || wq > 30) return;

    int mm[16];
    #pragma unroll
    for (int i = 0; i < 16; i++) mm[i] = 0;

    #pragma unroll
    for (int kh = 0; kh < 3; kh++){
        uint32_t xr[24];                       // [kw*8+q]
        #pragma unroll
        for (int q = 0; q < 8; q++)
            #pragma unroll
            for (int kw = 0; kw < 3; kw++)
                xr[kw*8 + q] = sx[q*102 + kh*34 + (wq - 1 + kw)];
        #pragma unroll
        for (int i = 0; i < 16; i++){
            const uint4* w4 = (const uint4*)&sw[(og*16 + i)*72 + kh*24];
            int acc = 0;
            #pragma unroll
            for (int v = 0; v < 6; v++){
                uint4 wv = w4[v];              // broadcast LDS.128 (same addr whole warp)
                acc += __popc(xr[4*v+0] ^ wv.x) + __popc(xr[4*v+1] ^ wv.y)
                     + __popc(xr[4*v+2] ^ wv.z) + __popc(xr[4*v+3] ^ wv.w);
            }
            mm[i] += acc;
        }
    }

    short* dst = &g_acc[which][(size_t)n*CCI*HWI + h*32 + wq];
    #pragma unroll
    for (int i = 0; i < 16; i++){
        int D = 2304 - 2*mm[i];
        D = D < -254 ? -254 : (D > 254 ? 254 : D);
        int o = ohalf*128 + og*16 + i;
        dst[(size_t)o*HWI] = (short)D;
    }
}

// ---------------- border: fused gather + quantized conv. grid <<<3968,256>>> ----------------
__global__ void k_border(int which){
    __shared__ unsigned long long sxp[NCHK], svm[NCHK];
    __shared__ int svc[NCHK];
    int blk = blockIdx.x;
    int n = blk / NBORD, b = blk % NBORD;
    int h, w; border_hw(b, h, w);
    int t = threadIdx.x;

    if (t < NCHK) sxp[t] = 0ull;
    __syncthreads();

    if (t < 144){                      // 4 threads per chunk, 16 bits each
        int j = t >> 2, q = t & 3;
        unsigned long long bits = 0ull;
        for (int bb = q*16; bb < q*16 + 16; bb++){
            int f = 64*j + bb;
            int c = f / 9, k = f - 9*c;
            int kh = k / 3, kw = k % 3;
            int hh = h + kh - 1, ww = w + kw - 1;
            if ((unsigned)hh < 32u && (unsigned)ww < 32u){
                uint32_t word = g_X32[which][(((n*32 + hh)*32 + ww) << 3) + (c >> 5)];
                bits |= (unsigned long long)((word >> (c & 31)) & 1u) << bb;
            }
        }
        atomicOr(&sxp[j], bits);
    } else if (t < 144 + NCHK){
        int j = t - 144;
        unsigned long long m = vmask_of(h, w, j);
        svm[j] = m;
        svc[j] = __popcll(m);
    }
    __syncthreads();

    int o = t;
    const unsigned long long* wp = &g_Wp64[which][o*NCHK];
    int acc = 0;
    #pragma unroll
    for (int j = 0; j < NCHK; j++){
        int mm = __popcll((sxp[j] ^ wp[j]) & svm[j]);
        int ps = svc[j] - 2*mm;
        acc += ps + ((ps & 1) ? ((ps & 2) - 1) : 0);
    }
    acc = acc < -254 ? -254 : (acc > 254 ? 254 : acc);
    g_acc[which][(size_t)(n*CCI + o)*HWI + h*32 + w] = (short)acc;
}

// ---------------- bn1: stats + coef fused. grid <<<256,512>>> ----------------
__global__ void k_bn1(const float* __restrict__ gamma, const float* __restrict__ beta){
    int c = blockIdx.x, t = threadIdx.x;
    int s = 0, q = 0;
    for (int n = 0; n < NNI; n++){
        uint32_t pk = *(const uint32_t*)&g_acc[0][(((size_t)n*CCI + c) << 10) + 2*t];
        int v0 = (short)(pk & 0xFFFF), v1 = (short)(pk >> 16);
        s += v0 + v1; q += v0*v0 + v1*v1;
    }
    __shared__ long long shs[16], shq[16];
    long long sl = wred_ll((long long)s), ql = wred_ll((long long)q);
    if ((t & 31) == 0){ shs[t >> 5] = sl; shq[t >> 5] = ql; }
    __syncthreads();
    if (t == 0){
        long long S = 0, Q = 0;
        for (int i = 0; i < 16; i++){ S += shs[i]; Q += shq[i]; }
        const double Nn = (double)(NNI*HWI);
        double m   = (double)S / Nn;
        double var = (double)Q / Nn - m*m;
        double A   = (1.0 / sqrt(var + 1e-5)) * (double)gamma[c];
        g_coef[c]       = (float)A;
        g_coef[CCI + c] = (float)((double)beta[c] - m*A);
    }
}

// ---------------- bn2: stats + coef fused (over clip(acc2)+x0). grid <<<256,512>>> ----------------
__global__ void k_bn2(const float* __restrict__ x0,
                      const float* __restrict__ gamma, const float* __restrict__ beta){
    int c = blockIdx.x, t = threadIdx.x;
    double s = 0.0, q = 0.0;
    for (int n = 0; n < NNI; n++){
        size_t base = (((size_t)n*CCI + c) << 10) + 2*t;
        uint32_t pk = *(const uint32_t*)&g_acc[1][base];
        float2 xv = *(const float2*)&x0[base];
        double y0 = (double)(short)(pk & 0xFFFF) + (double)xv.x;
        double y1 = (double)(short)(pk >> 16)    + (double)xv.y;
        s += y0 + y1; q += y0*y0 + y1*y1;
    }
    __shared__ double shs[16], shq[16];
    s = wred_d(s); q = wred_d(q);
    if ((t & 31) == 0){ shs[t >> 5] = s; shq[t >> 5] = q; }
    __syncthreads();
    if (t == 0){
        double S = 0, Q = 0;
        for (int i = 0; i < 16; i++){ S += shs[i]; Q += shq[i]; }
        const double Nn = (double)(NNI*HWI);
        double m   = S / Nn;
        double var = Q / Nn - m*m;
        double A   = (1.0 / sqrt(var + 1e-5)) * (double)gamma[c];
        g_coef[2*CCI + c] = (float)A;
        g_coef[3*CCI + c] = (float)((double)beta[c] - m*A);
    }
}

// ---------------- final: bn2 + hardtanh. grid <<<8192,256>>> ----------------
__global__ void k_final(const float* __restrict__ x0, float* __restrict__ out){
    int blk = blockIdx.x;
    int c = blk & (CCI - 1);
    float A = g_coef[2*CCI + c], B = g_coef[3*CCI + c];
    const short* a2 = &g_acc[1][(size_t)blk*HWI];
    const float* xs = x0 + (size_t)blk*HWI;
    float* dst = out + (size_t)blk*HWI;
    for (int i = threadIdx.x; i < HWI; i += 256){
        float y = (float)a2[i] + xs[i];
        float z = A*y + B;
        dst[i] = fminf(1.f, fmaxf(-1.f, z));
    }
}

// ---------------- regularizer. <<<1,256>>> ----------------
__global__ void k_reg(const float* __restrict__ reg0, float* __restrict__ out, int out_size){
    int t = threadIdx.x, cnt = 0;
    for (int i = t; i < HWI*NCHK; i += 256) cnt += (int)(__popcll(g_Vm[i]) & 1ull);
    __shared__ int sh[8];
    cnt = wred_i(cnt);
    if ((t & 31) == 0) sh[t >> 5] = cnt;
    __syncthreads();
    if (t == 0){
        int T = 0;
        for (int i = 0; i < 8; i++) T += sh[i];
        out[out_size - 1] = reg0[0] + 3.0f * (float)T / 1024.0f;
    }
}

// ---------------- launch ----------------
extern "C" void kernel_launch(void* const* d_in, const int* in_sizes, int n_in,
                              void* d_out, int out_size){
    const float* x0     = (const float*)d_in[0];
    const float* reg0   = (const float*)d_in[1];
    const float* w1     = (const float*)d_in[2];
    const float* gamma1 = (const float*)d_in[3];
    const float* beta1  = (const float*)d_in[4];
    const float* w2     = (const float*)d_in[5];
    const float* gamma2 = (const float*)d_in[6];
    const float* beta2  = (const float*)d_in[7];
    float* out = (float*)d_out;

    k_pack_w<<<512, 128>>>(w1, w2);          // 0
    k_vmask<<<HWI, NCHK>>>();                // 1
    k_pack_x1<<<1024, 256>>>(x0);            // 2
    k_conv_int<<<NNI*30*2, 256>>>(0);        // 3  <-- profiled slot
    k_border<<<NNI*NBORD, 256>>>(0);         // 4
    k_bn1<<<256, 512>>>(gamma1, beta1);      // 5
    k_pack_x2<<<1024, 256>>>();              // 6
    k_conv_int<<<NNI*30*2, 256>>>(1);        // 7
    k_border<<<NNI*NBORD, 256>>>(1);         // 8
    k_bn2<<<256, 512>>>(x0, gamma2, beta2);  // 9
    k_final<<<NNI*CCI, 256>>>(x0, out);      // 10
    k_reg<<<1, 256>>>(reg0, out, out_size);  // 11
}